// round 6
// baseline (speedup 1.0000x reference)
#include <cuda_runtime.h>
#include <cuda_bf16.h>
#include <cstdint>

// CTC loss forward, fused single-kernel producer/consumer.
// 32 CTAs (one per batch), 256 threads:
//   warp 0   : alpha recurrence, 7 trellis positions per lane, per-lane
//              block-floating-point, renorm every 2 steps.
//   warps 1-7: emit-row producers. Warp pw OWNS ring slot pw (chunk % 7 == pw)
//              so every mbarrier is observed within a 1-phase window and
//              parity waits are sound (round-5 bug: stride 7 > 5 slots).
// Ring: 7 slots x 14 rows x 256 floats, full/empty mbarriers (count=32).

#define TT 1000
#define BB 32
#define CC 1000
#define SS 100
#define LL 201                 // 2*SS+1
#define CH 14                  // rows per ring slot
#define NSLOT 7                // == number of producer warps (static ownership)
#define NCHUNK ((TT - 1 + CH - 1) / CH)   // 72
#define RING_F (NSLOT * CH * 256)         // 25088 floats
#define STAGE_F (7 * 1024)                // 7168 floats
#define SMEM_BYTES ((RING_F + STAGE_F) * 4 + 2 * NSLOT * 8)

#define LOG2E_F 1.4426950408889634f
#define LN2_F 0.6931471805599453f
#define EDEAD (-(1 << 28))

__device__ float g_loss[BB];

__device__ __forceinline__ float fast_ex2(float x) {
    float y; asm("ex2.approx.ftz.f32 %0, %1;" : "=f"(y) : "f"(x)); return y;
}
__device__ __forceinline__ float fast_lg2(float x) {
    float y; asm("lg2.approx.f32 %0, %1;" : "=f"(y) : "f"(x)); return y;
}
__device__ __forceinline__ uint32_t s2u(const void* p) {
    return (uint32_t)__cvta_generic_to_shared(p);
}
__device__ __forceinline__ void mbar_init(uint64_t* mb, uint32_t cnt) {
    asm volatile("mbarrier.init.shared.b64 [%0], %1;" :: "r"(s2u(mb)), "r"(cnt) : "memory");
}
__device__ __forceinline__ void mbar_wait(uint64_t* mb, uint32_t parity) {
    asm volatile(
        "{\n\t.reg .pred P;\n\t"
        "WL%=:\n\t"
        "mbarrier.try_wait.parity.acquire.cta.shared::cta.b64 P, [%0], %1, 0x989680;\n\t"
        "@P bra WD%=;\n\t"
        "bra WL%=;\n\t"
        "WD%=:\n\t}"
        :: "r"(s2u(mb)), "r"(parity) : "memory");
}
__device__ __forceinline__ void mbar_arrive(uint64_t* mb) {
    asm volatile("mbarrier.arrive.shared.b64 _, [%0];" :: "r"(s2u(mb)) : "memory");
}
// exact 2^d for d <= 0 (flushes to 0 below 2^-127)
__device__ __forceinline__ float pow2_clamped(int d) {
    int u = 127 + d; if (u < 0) u = 0;
    return __uint_as_float((unsigned)u << 23);
}

// final-loss: alpha at end positions, (mantissa, exponent) pair-reduce
__device__ __forceinline__ void emit_loss(int b, const float a[7], int E,
                                          int lane, int end1, int end2) {
    float c = 0.0f;
#pragma unroll
    for (int j = 0; j < 7; j++) {
        int l = 7 * lane + j;
        if (l == end1 || l == end2) c += a[j];
    }
    int Ec = (c > 0.0f) ? E : EDEAD;
#pragma unroll
    for (int o = 16; o > 0; o >>= 1) {
        float co = __shfl_xor_sync(~0u, c, o);
        int   Eo = __shfl_xor_sync(~0u, Ec, o);
        int   Em = (Ec > Eo) ? Ec : Eo;
        c = c * pow2_clamped(Ec - Em) + co * pow2_clamped(Eo - Em);
        Ec = Em;
    }
    if (lane == 0) {
        float lv = -(fast_lg2(c) + (float)Ec) * LN2_F;
        if (!(lv <= 0.5e30f)) lv = 0.0f;   // zero_infinity (inf/nan)
        g_loss[b] = lv;
    }
}

__global__ void __launch_bounds__(256, 1)
ctc_fused(const float* __restrict__ logp,
          const int* __restrict__ targets,
          const int* __restrict__ input_lens,
          const int* __restrict__ target_lens) {
    extern __shared__ __align__(16) float dsm[];
    float* ring = dsm;                              // RING_F floats
    float* stage = dsm + RING_F;                    // STAGE_F floats
    uint64_t* mbf = (uint64_t*)(stage + STAGE_F);   // NSLOT full barriers
    uint64_t* mbe = mbf + NSLOT;                    // NSLOT empty barriers

    const int b = blockIdx.x;
    const int tid = threadIdx.x;
    const int wid = tid >> 5;
    const int lane = tid & 31;

    const int il_m1 = input_lens[b] - 1;
    const int tl = target_lens[b];
    const int Lv = 2 * tl + 1;
    const int end1 = 2 * tl, end2 = 2 * tl - 1;

    if (tid == 0) {
        for (int q = 0; q < NSLOT; q++) { mbar_init(&mbf[q], 32); mbar_init(&mbe[q], 32); }
    }
    __syncthreads();

    if (wid == 0) {
        // ================= consumer =================
        float s[7];
#pragma unroll
        for (int j = 0; j < 7; j++) {
            int l = 7 * lane + j;
            float sv = 0.0f;
            if ((l & 1) && l < LL) {
                int si = (l - 1) >> 1;
                if (si > 0) {
                    int c0 = targets[b * SS + si];
                    int c1 = targets[b * SS + si - 1];
                    sv = (c0 != 0 && c0 != c1) ? 1.0f : 0.0f;
                }
            }
            s[j] = sv;
        }

        // t = 0 init
        float a[7];
#pragma unroll
        for (int j = 0; j < 7; j++) a[j] = 0.0f;
        int E = 0;
        if (lane == 0) {
            const float* row0 = logp + (long)b * CC;
            a[0] = fast_ex2(row0[0] * LOG2E_F);
            if (Lv > 1) a[1] = fast_ex2(row0[targets[b * SS]] * LOG2E_F);
        }
        if (il_m1 == 0) emit_loss(b, a, E, lane, end1, end2);

        int t = 1;
        for (int c = 0; c < NCHUNK; c++) {
            int slot = c % NSLOT;
            mbar_wait(&mbf[slot], (uint32_t)((c / NSLOT) & 1));
            int rows = TT - (1 + c * CH); if (rows > CH) rows = CH;
            const float4* ep4 = (const float4*)(ring + slot * CH * 256) + lane * 2;
#pragma unroll 2
            for (int r = 0; r < rows; r++, t++) {
                float4 e0 = ep4[r * 64];
                float4 e1 = ep4[r * 64 + 1];

                float p6 = __shfl_up_sync(~0u, a[6], 1);
                float p5 = __shfl_up_sync(~0u, a[5], 1);
                int   Ep = __shfl_up_sync(~0u, E, 1);
                if (lane == 0) { p5 = 0.0f; p6 = 0.0f; }

                int Em = (E > Ep) ? E : Ep;
                float sa = pow2_clamped(E - Em);
                float sp = pow2_clamped(Ep - Em);
                p6 *= sp; p5 *= sp;
#pragma unroll
                for (int j = 0; j < 7; j++) a[j] *= sa;

                float n0 = fmaf(s[0], p5, a[0] + p6) * e0.x;
                float n1 = fmaf(s[1], p6, a[1] + a[0]) * e0.y;
                float n2 = fmaf(s[2], a[0], a[2] + a[1]) * e0.z;
                float n3 = fmaf(s[3], a[1], a[3] + a[2]) * e0.w;
                float n4 = fmaf(s[4], a[2], a[4] + a[3]) * e1.x;
                float n5 = fmaf(s[5], a[3], a[5] + a[4]) * e1.y;
                float n6 = fmaf(s[6], a[4], a[6] + a[5]) * e1.z;

                if ((t & 1) == 0) {
                    float m = fmaxf(fmaxf(fmaxf(n0, n1), fmaxf(n2, n3)),
                                    fmaxf(fmaxf(n4, n5), n6));
                    unsigned u = __float_as_uint(m) >> 23;
                    int shift = 127 - (int)u;
                    if (shift > 127) shift = 127;      // dead lane clamp
                    float f = __uint_as_float((unsigned)(shift + 127) << 23);
                    E = Em - shift;
                    a[0] = n0 * f; a[1] = n1 * f; a[2] = n2 * f; a[3] = n3 * f;
                    a[4] = n4 * f; a[5] = n5 * f; a[6] = n6 * f;
                } else {
                    E = Em;
                    a[0] = n0; a[1] = n1; a[2] = n2; a[3] = n3;
                    a[4] = n4; a[5] = n5; a[6] = n6;
                }

                if (t == il_m1) emit_loss(b, a, E, lane, end1, end2);
            }
            mbar_arrive(&mbe[slot]);
        }
    } else {
        // ================= producers (warps 1..7, warp pw owns slot pw) =====
        const int pw = wid - 1;
        float* stg = stage + pw * 1024;
        float4* stg4 = (float4*)stg;

        int code[7], lab[7];
#pragma unroll
        for (int j = 0; j < 7; j++) {
            int l = 7 * lane + j;
            code[j] = 0; lab[j] = 0;
            if (l < Lv) {
                if (l & 1) { code[j] = 2; lab[j] = targets[b * SS + ((l - 1) >> 1)]; }
                else code[j] = 1;
            }
        }

        for (int c = pw; c < NCHUNK; c += NSLOT) {
            const int slot = pw;                 // static ownership: c % 7 == pw
            int round = c / NSLOT;
            mbar_wait(&mbe[slot], (uint32_t)((round & 1) ^ 1));
            int t0 = 1 + c * CH;
            int rows = TT - t0; if (rows > CH) rows = CH;
            for (int r = 0; r < rows; r++) {
                int t = t0 + r;
                const float4* rowp = (const float4*)(logp + ((long)t * BB + b) * CC);
#pragma unroll
                for (int q = 0; q < 8; q++) {
                    int idx = q * 32 + lane;
                    if (idx < 250) stg4[idx] = rowp[idx];
                }
                __syncwarp();
                float eb = fast_ex2(stg[0] * LOG2E_F);
                float o[8];
#pragma unroll
                for (int j = 0; j < 7; j++) {
                    float v = 0.0f;
                    if (code[j] == 2) v = fast_ex2(stg[lab[j]] * LOG2E_F);
                    else if (code[j] == 1) v = eb;
                    o[j] = v;
                }
                o[7] = 0.0f;
                float4* dst = (float4*)(ring + (slot * CH + r) * 256 + lane * 8);
                dst[0] = make_float4(o[0], o[1], o[2], o[3]);
                dst[1] = make_float4(o[4], o[5], o[6], o[7]);
                __syncwarp();   // staging reuse guard
            }
            mbar_arrive(&mbf[slot]);   // release: ring stores visible to consumer
        }
    }
}

__global__ void ctc_reduce_kernel(float* __restrict__ out) {
    if (threadIdx.x == 0) {
        float sum = 0.0f;
        for (int i = 0; i < BB; i++) sum += g_loss[i];
        out[0] = sum;
    }
}

// no-op padding so ncu's fixed "-s 5 -c 1" lands on ctc_fused (5 kernels/call,
// 6th kernel execution = ctc_fused of replay 2). Removed once profiled.
__global__ void ctc_nop() {}

extern "C" void kernel_launch(void* const* d_in, const int* in_sizes, int n_in,
                              void* d_out, int out_size) {
    const float* logp        = (const float*)d_in[0];
    const int*   targets     = (const int*)d_in[1];
    const int*   input_lens  = (const int*)d_in[2];
    const int*   target_lens = (const int*)d_in[3];
    float* out = (float*)d_out;

    cudaFuncSetAttribute(ctc_fused, cudaFuncAttributeMaxDynamicSharedMemorySize, SMEM_BYTES);
    ctc_fused<<<BB, 256, SMEM_BYTES>>>(logp, targets, input_lens, target_lens);
    ctc_reduce_kernel<<<1, 32>>>(out);
    ctc_nop<<<1, 32>>>();
    ctc_nop<<<1, 32>>>();
    ctc_nop<<<1, 32>>>();
}

// round 7
// speedup vs baseline: 2.4643x; 2.4643x over previous
#include <cuda_runtime.h>
#include <cuda_bf16.h>
#include <cstdint>

// CTC loss forward, fused kernel with forward/backward meet-in-the-middle.
// 32 CTAs (one per batch), 320 threads:
//   wid 8: forward alpha scan  t = 1 .. m        (m = (il-1)/2)
//   wid 9: backward gamma scan t = il-1 .. m+1   (independent chain, runs
//          concurrently -> serial length halved)
//   wid 0-3: forward emit-row producers (direct GMEM gather, slot = wid)
//   wid 4-7: backward emit-row producers (slot = wid-4)
// loss = -log( sum_l alpha_m[l] * gamma_m[l] ), per-lane block floating point
// everywhere (mantissa regs + int exponent, exact power-of-2 rebasing).

#define TT 1000
#define BB 32
#define CC 1000
#define SS 100
#define LL 201
#define CH 14
#define NSLOT 4
#define RING_F_DIR (NSLOT * CH * 256)          // floats per direction
#define SMEM_BYTES (2 * RING_F_DIR * 4 + 256 * 4 + 32 * 4 + 16 * 8)

#define LOG2E_F 1.4426950408889634f
#define LN2_F 0.6931471805599453f
#define EDEAD (-(1 << 28))

__device__ float g_loss[BB];

__device__ __forceinline__ float fast_ex2(float x) {
    float y; asm("ex2.approx.ftz.f32 %0, %1;" : "=f"(y) : "f"(x)); return y;
}
__device__ __forceinline__ float fast_lg2(float x) {
    float y; asm("lg2.approx.f32 %0, %1;" : "=f"(y) : "f"(x)); return y;
}
__device__ __forceinline__ uint32_t s2u(const void* p) {
    return (uint32_t)__cvta_generic_to_shared(p);
}
__device__ __forceinline__ void mbar_init(uint64_t* mb, uint32_t cnt) {
    asm volatile("mbarrier.init.shared.b64 [%0], %1;" :: "r"(s2u(mb)), "r"(cnt) : "memory");
}
__device__ __forceinline__ void mbar_wait(uint64_t* mb, uint32_t parity) {
    asm volatile(
        "{\n\t.reg .pred P;\n\t"
        "WL%=:\n\t"
        "mbarrier.try_wait.parity.acquire.cta.shared::cta.b64 P, [%0], %1, 0x989680;\n\t"
        "@P bra WD%=;\n\t"
        "bra WL%=;\n\t"
        "WD%=:\n\t}"
        :: "r"(s2u(mb)), "r"(parity) : "memory");
}
__device__ __forceinline__ void mbar_arrive(uint64_t* mb) {
    asm volatile("mbarrier.arrive.shared.b64 _, [%0];" :: "r"(s2u(mb)) : "memory");
}
// exact 2^d for d <= 0 (flushes to 0 below 2^-127)
__device__ __forceinline__ float pow2_clamped(int d) {
    int u = 127 + d; if (u < 0) u = 0;
    return __uint_as_float((unsigned)u << 23);
}

// producer: direct-gather emit rows into ring slot `pw` (static ownership)
__device__ __forceinline__ void produce_rows(
    const float* __restrict__ logp, int b, float* ring,
    uint64_t* mbf, uint64_t* mbe, int nchunk, int pw,
    int tfirst, int dir, int ntotal,
    const int off[7], const int msk[7], int lane)
{
    for (int c = pw; c < nchunk; c += NSLOT) {
        int round = c / NSLOT;
        mbar_wait(&mbe[pw], (uint32_t)((round & 1) ^ 1));
        int rows = ntotal - c * CH; if (rows > CH) rows = CH;
        int trow0 = tfirst + dir * (c * CH);
        float* slotbase = ring + pw * (CH * 256) + lane * 8;
        for (int r = 0; r < rows; r += 2) {
            int t0 = trow0 + dir * r;
            const float* rp0 = logp + ((long)t0 * BB + b) * CC;
            bool two = (r + 1) < rows;
            int t1 = trow0 + dir * (r + 1);
            const float* rp1 = logp + ((long)t1 * BB + b) * CC;
            float lp0[7], lp1[7];
#pragma unroll
            for (int j = 0; j < 7; j++) lp0[j] = __ldg(rp0 + off[j]);
#pragma unroll
            for (int j = 0; j < 7; j++) lp1[j] = two ? __ldg(rp1 + off[j]) : 0.0f;
            float o0[8], o1[8];
#pragma unroll
            for (int j = 0; j < 7; j++) {
                o0[j] = msk[j] ? fast_ex2(lp0[j] * LOG2E_F) : 0.0f;
                o1[j] = msk[j] ? fast_ex2(lp1[j] * LOG2E_F) : 0.0f;
            }
            o0[7] = 0.0f; o1[7] = 0.0f;
            float4* d0 = (float4*)(slotbase + r * 256);
            d0[0] = make_float4(o0[0], o0[1], o0[2], o0[3]);
            d0[1] = make_float4(o0[4], o0[5], o0[6], o0[7]);
            if (two) {
                float4* d1 = (float4*)(slotbase + (r + 1) * 256);
                d1[0] = make_float4(o1[0], o1[1], o1[2], o1[3]);
                d1[1] = make_float4(o1[4], o1[5], o1[6], o1[7]);
            }
        }
        mbar_arrive(&mbf[pw]);
    }
}

__global__ void __launch_bounds__(320, 1)
ctc_fused(const float* __restrict__ logp,
          const int* __restrict__ targets,
          const int* __restrict__ input_lens,
          const int* __restrict__ target_lens) {
    extern __shared__ __align__(16) float dsm[];
    float* fring = dsm;
    float* bring = dsm + RING_F_DIR;
    float* xu = bring + RING_F_DIR;            // 256 floats
    int* xE = (int*)(xu + 256);                // 32 ints
    uint64_t* mbfF = (uint64_t*)(xE + 32);     // 4
    uint64_t* mbeF = mbfF + NSLOT;
    uint64_t* mbfB = mbeF + NSLOT;
    uint64_t* mbeB = mbfB + NSLOT;

    const int b = blockIdx.x;
    const int tid = threadIdx.x;
    const int wid = tid >> 5;
    const int lane = tid & 31;

    const int il = input_lens[b];
    const int tl = target_lens[b];
    const int Lv = 2 * tl + 1;
    const int end1 = 2 * tl, end2 = 2 * tl - 1;
    const int m = (il - 1) >> 1;
    const int nF = m;                 // forward rows t=1..m
    const int nB = il - 1 - m;        // backward rows t=il-1 .. m+1
    const int ncF = (nF + CH - 1) / CH;
    const int ncB = (nB + CH - 1) / CH;
    const bool combine = (il > 1);

    if (tid == 0) {
        for (int q = 0; q < NSLOT; q++) {
            mbar_init(&mbfF[q], 32); mbar_init(&mbeF[q], 32);
            mbar_init(&mbfB[q], 32); mbar_init(&mbeB[q], 32);
        }
    }
    __syncthreads();

    if (wid < 8) {
        // ---------------- producers ----------------
        int off[7], msk[7];
#pragma unroll
        for (int j = 0; j < 7; j++) {
            int l = 7 * lane + j;
            off[j] = 0; msk[j] = 0;
            if (l < Lv) {
                msk[j] = 1;
                if (l & 1) off[j] = targets[b * SS + ((l - 1) >> 1)];
            }
        }
        if (wid < 4)
            produce_rows(logp, b, fring, mbfF, mbeF, ncF, wid, 1, +1, nF, off, msk, lane);
        else
            produce_rows(logp, b, bring, mbfB, mbeB, ncB, wid - 4, il - 1, -1, nB, off, msk, lane);
        return;
    }

    // shared by both consumers: skip flags
    if (wid == 8) {
        // ================= forward consumer =================
        float s[7];        // skip INTO own position
#pragma unroll
        for (int j = 0; j < 7; j++) {
            int l = 7 * lane + j;
            float sv = 0.0f;
            if ((l & 1) && l < LL) {
                int si = (l - 1) >> 1;
                if (si > 0) {
                    int c0 = targets[b * SS + si];
                    int c1 = targets[b * SS + si - 1];
                    sv = (c0 != 0 && c0 != c1) ? 1.0f : 0.0f;
                }
            }
            s[j] = sv;
        }

        float a[7];
#pragma unroll
        for (int j = 0; j < 7; j++) a[j] = 0.0f;
        int E = 0;
        if (lane == 0) {
            const float* row0 = logp + (long)b * CC;
            a[0] = fast_ex2(row0[0] * LOG2E_F);
            if (Lv > 1) a[1] = fast_ex2(row0[targets[b * SS]] * LOG2E_F);
        }

        int t = 1;
        for (int c = 0; c < ncF; c++) {
            int slot = c % NSLOT;
            mbar_wait(&mbfF[slot], (uint32_t)((c / NSLOT) & 1));
            int rows = nF - c * CH; if (rows > CH) rows = CH;
            const float4* ep4 = (const float4*)(fring + slot * CH * 256) + lane * 2;
#pragma unroll 2
            for (int r = 0; r < rows; r++, t++) {
                float4 e0 = ep4[r * 64];
                float4 e1 = ep4[r * 64 + 1];

                float p6 = __shfl_up_sync(~0u, a[6], 1);
                float p5 = __shfl_up_sync(~0u, a[5], 1);
                int   Ep = __shfl_up_sync(~0u, E, 1);
                if (lane == 0) { p5 = 0.0f; p6 = 0.0f; }

                int Em = (E > Ep) ? E : Ep;
                float sa = pow2_clamped(E - Em);
                float sp = pow2_clamped(Ep - Em);
                p6 *= sp; p5 *= sp;
#pragma unroll
                for (int j = 0; j < 7; j++) a[j] *= sa;

                float n0 = fmaf(s[0], p5, a[0] + p6) * e0.x;
                float n1 = fmaf(s[1], p6, a[1] + a[0]) * e0.y;
                float n2 = fmaf(s[2], a[0], a[2] + a[1]) * e0.z;
                float n3 = fmaf(s[3], a[1], a[3] + a[2]) * e0.w;
                float n4 = fmaf(s[4], a[2], a[4] + a[3]) * e1.x;
                float n5 = fmaf(s[5], a[3], a[5] + a[4]) * e1.y;
                float n6 = fmaf(s[6], a[4], a[6] + a[5]) * e1.z;

                if ((t & 1) == 0) {
                    float mm = fmaxf(fmaxf(fmaxf(n0, n1), fmaxf(n2, n3)),
                                     fmaxf(fmaxf(n4, n5), n6));
                    unsigned u = __float_as_uint(mm) >> 23;
                    int shift = 127 - (int)u;
                    if (shift > 127) shift = 127;
                    float f = __uint_as_float((unsigned)(shift + 127) << 23);
                    E = Em - shift;
                    a[0] = n0 * f; a[1] = n1 * f; a[2] = n2 * f; a[3] = n3 * f;
                    a[4] = n4 * f; a[5] = n5 * f; a[6] = n6 * f;
                } else {
                    E = Em;
                    a[0] = n0; a[1] = n1; a[2] = n2; a[3] = n3;
                    a[4] = n4; a[5] = n5; a[6] = n6;
                }
            }
            mbar_arrive(&mbeF[slot]);
        }

        // ---- meet: wait for backward warp's u_{m+1} / E ----
        asm volatile("bar.sync 1, 64;" ::: "memory");

        float g[7];
        int Egam;
        if (combine) {
            float uu[7];
#pragma unroll
            for (int j = 0; j < 7; j++) uu[j] = xu[lane * 8 + j];
            float u7 = (lane < 31) ? xu[(lane + 1) * 8 + 0] : 0.0f;
            float u8 = (lane < 31) ? xu[(lane + 1) * 8 + 1] : 0.0f;
            int Eb = xE[lane];
            int Ebn = (lane < 31) ? xE[lane + 1] : Eb;
            int Em2 = (Eb > Ebn) ? Eb : Ebn;
            float su = pow2_clamped(Eb - Em2);
            float sn = pow2_clamped(Ebn - Em2);
            u7 *= sn; u8 *= sn;
            // skip INTO position l+2 (same flag array as backward consumer)
            float sB[7];
#pragma unroll
            for (int j = 0; j < 7; j++) {
                int p2 = 7 * lane + j + 2;
                float sv = 0.0f;
                if ((p2 & 1) && p2 < Lv) {
                    int si = (p2 - 1) >> 1;
                    if (si > 0) {
                        int c0 = targets[b * SS + si];
                        int c1 = targets[b * SS + si - 1];
                        sv = (c0 != 0 && c0 != c1) ? 1.0f : 0.0f;
                    }
                }
                sB[j] = sv;
            }
#pragma unroll
            for (int j = 0; j < 5; j++)
                g[j] = su * fmaf(sB[j], uu[j + 2], uu[j] + uu[j + 1]);
            g[5] = fmaf(sB[5], u7, su * (uu[5] + uu[6]));
            g[6] = su * uu[6] + fmaf(sB[6], u8, u7);
            Egam = Em2;
        } else {
#pragma unroll
            for (int j = 0; j < 7; j++) {
                int l = 7 * lane + j;
                g[j] = (l == end1 || l == end2) ? 1.0f : 0.0f;
            }
            Egam = 0;
        }

        float cacc = 0.0f;
#pragma unroll
        for (int j = 0; j < 7; j++) cacc = fmaf(a[j], g[j], cacc);
        int Ec = (cacc > 0.0f) ? (E + Egam) : EDEAD;
#pragma unroll
        for (int o = 16; o > 0; o >>= 1) {
            float co = __shfl_xor_sync(~0u, cacc, o);
            int   Eo = __shfl_xor_sync(~0u, Ec, o);
            int   Emx = (Ec > Eo) ? Ec : Eo;
            cacc = cacc * pow2_clamped(Ec - Emx) + co * pow2_clamped(Eo - Emx);
            Ec = Emx;
        }
        if (lane == 0) {
            float lv = -(fast_lg2(cacc) + (float)Ec) * LN2_F;
            if (!(lv <= 0.5e30f)) lv = 0.0f;   // zero_infinity (inf/nan)
            g_loss[b] = lv;
        }
    } else {
        // ================= backward consumer =================
        float sB[7];       // skip INTO position l+2
        float ind[7];
#pragma unroll
        for (int j = 0; j < 7; j++) {
            int l = 7 * lane + j;
            ind[j] = (l == end1 || l == end2) ? 1.0f : 0.0f;
            int p2 = l + 2;
            float sv = 0.0f;
            if ((p2 & 1) && p2 < Lv) {
                int si = (p2 - 1) >> 1;
                if (si > 0) {
                    int c0 = targets[b * SS + si];
                    int c1 = targets[b * SS + si - 1];
                    sv = (c0 != 0 && c0 != c1) ? 1.0f : 0.0f;
                }
            }
            sB[j] = sv;
        }

        float u[7];
#pragma unroll
        for (int j = 0; j < 7; j++) u[j] = 0.0f;
        int E = 0;
        int k = 0;         // processed-row counter (for renorm cadence)
        bool first = true;

        for (int c = 0; c < ncB; c++) {
            int slot = c % NSLOT;
            mbar_wait(&mbfB[slot], (uint32_t)((c / NSLOT) & 1));
            int rows = nB - c * CH; if (rows > CH) rows = CH;
            const float4* ep4 = (const float4*)(bring + slot * CH * 256) + lane * 2;
#pragma unroll 2
            for (int r = 0; r < rows; r++) {
                float4 e0 = ep4[r * 64];
                float4 e1 = ep4[r * 64 + 1];
                float n0, n1, n2, n3, n4, n5, n6;
                int Em;
                if (first) {
                    first = false;
                    n0 = e0.x * ind[0]; n1 = e0.y * ind[1]; n2 = e0.z * ind[2];
                    n3 = e0.w * ind[3]; n4 = e1.x * ind[4]; n5 = e1.y * ind[5];
                    n6 = e1.z * ind[6];
                    Em = 0;
                } else {
                    float q0 = __shfl_down_sync(~0u, u[0], 1);
                    float q1 = __shfl_down_sync(~0u, u[1], 1);
                    int   Eq = __shfl_down_sync(~0u, E, 1);
                    if (lane == 31) { q0 = 0.0f; q1 = 0.0f; }

                    Em = (E > Eq) ? E : Eq;
                    float sa = pow2_clamped(E - Em);
                    float sq = pow2_clamped(Eq - Em);
                    q0 *= sq; q1 *= sq;
#pragma unroll
                    for (int j = 0; j < 7; j++) u[j] *= sa;

                    n0 = fmaf(sB[0], u[2], u[0] + u[1]) * e0.x;
                    n1 = fmaf(sB[1], u[3], u[1] + u[2]) * e0.y;
                    n2 = fmaf(sB[2], u[4], u[2] + u[3]) * e0.z;
                    n3 = fmaf(sB[3], u[5], u[3] + u[4]) * e0.w;
                    n4 = fmaf(sB[4], u[6], u[4] + u[5]) * e1.x;
                    n5 = fmaf(sB[5], q0, u[5] + u[6]) * e1.y;
                    n6 = fmaf(sB[6], q1, u[6] + q0) * e1.z;
                }

                if ((k & 1) == 1) {
                    float mm = fmaxf(fmaxf(fmaxf(n0, n1), fmaxf(n2, n3)),
                                     fmaxf(fmaxf(n4, n5), n6));
                    unsigned uu = __float_as_uint(mm) >> 23;
                    int shift = 127 - (int)uu;
                    if (shift > 127) shift = 127;
                    float f = __uint_as_float((unsigned)(shift + 127) << 23);
                    E = Em - shift;
                    u[0] = n0 * f; u[1] = n1 * f; u[2] = n2 * f; u[3] = n3 * f;
                    u[4] = n4 * f; u[5] = n5 * f; u[6] = n6 * f;
                } else {
                    E = Em;
                    u[0] = n0; u[1] = n1; u[2] = n2; u[3] = n3;
                    u[4] = n4; u[5] = n5; u[6] = n6;
                }
                k++;
            }
            mbar_arrive(&mbeB[slot]);
        }

        if (!combine) {     // il == 1: gamma_m is the raw end indicator
#pragma unroll
            for (int j = 0; j < 7; j++) u[j] = ind[j];
            E = 0;
        }
#pragma unroll
        for (int j = 0; j < 7; j++) xu[lane * 8 + j] = u[j];
        xu[lane * 8 + 7] = 0.0f;
        xE[lane] = E;
        asm volatile("bar.sync 1, 64;" ::: "memory");
    }
}

__global__ void ctc_reduce_kernel(float* __restrict__ out) {
    if (threadIdx.x == 0) {
        float sum = 0.0f;
        for (int i = 0; i < BB; i++) sum += g_loss[i];
        out[0] = sum;
    }
}

// padding so ncu's fixed skip lands on ctc_fused (profiled launch = stream
// index 3; three nops first => idx3 = ctc_fused). Diagnostic; removable.
__global__ void ctc_nop() {}

extern "C" void kernel_launch(void* const* d_in, const int* in_sizes, int n_in,
                              void* d_out, int out_size) {
    const float* logp        = (const float*)d_in[0];
    const int*   targets     = (const int*)d_in[1];
    const int*   input_lens  = (const int*)d_in[2];
    const int*   target_lens = (const int*)d_in[3];
    float* out = (float*)d_out;

    cudaFuncSetAttribute(ctc_fused, cudaFuncAttributeMaxDynamicSharedMemorySize, SMEM_BYTES);
    ctc_nop<<<1, 32>>>();
    ctc_nop<<<1, 32>>>();
    ctc_nop<<<1, 32>>>();
    ctc_fused<<<BB, 320, SMEM_BYTES>>>(logp, targets, input_lens, target_lens);
    ctc_reduce_kernel<<<1, 32>>>(out);
}